// round 1
// baseline (speedup 1.0000x reference)
#include <cuda_runtime.h>
#include <cuda_bf16.h>
#include <math_constants.h>

// MiniRocket on GB300-class GPU.
// Inputs: d_in[0] = x (64*8*1024 f32), d_in[1] = biases (9996 f32),
//         d_in[2] = channel_indices (336*3 int32)
// Output: d_out = (64, 9996) f32.
//
// Decomposition: conv weight = -1 everywhere + 3 at the 3 chosen taps, so
//   conv_c,j(l) = 3*tapsum_c,j(l) - S_c(l),  S_c = 9-tap dilated sum.
// csum_j(l) = sum over the 3 selected channels. PPV = mean(csum > bias) over
// full length (even i+j parity) or interior [p, L-p) (odd parity).

#define NSAMP 64
#define NCH   8
#define LEN   1024
#define NKER  84
#define PADW  32              // max pad = 4*8
#define XPITCH (LEN + 2*PADW) // 1088
#define TOTF  9996

__global__ __launch_bounds__(384)
void minirocket_kernel(const float* __restrict__ x,
                       const float* __restrict__ biases,
                       const int* __restrict__ ci,
                       float* __restrict__ out)
{
    extern __shared__ float sm[];
    float* Xp = sm;                       // [NCH][XPITCH]  zero-padded signal
    float* S  = sm + NCH * XPITCH;        // [NCH][LEN]     9-tap dilated sums
    int* comb = (int*)(S + NCH * LEN);    // [84] packed tap triples

    const int i = blockIdx.x;             // dilation index 0..3
    const int n = blockIdx.y;             // sample
    const int d = 1 << i;                 // dilation 1,2,4,8
    const int p = 4 * d;                  // conv padding
    const int tid = threadIdx.x;

    // ---- generate the 84 lexicographic 3-combinations of 0..8 ----
    if (tid < NKER) {
        int t = 0, aa = 0, bb = 0, cc = 0;
        for (int x0 = 0; x0 < 9; x0++)
            for (int x1 = x0 + 1; x1 < 9; x1++)
                for (int x2 = x1 + 1; x2 < 9; x2++) {
                    if (t == tid) { aa = x0; bb = x1; cc = x2; }
                    t++;
                }
        comb[tid] = aa | (bb << 8) | (cc << 16);
    }

    // ---- stage x[n] into smem with zero padding ----
    for (int k = tid; k < NCH * XPITCH; k += blockDim.x) {
        int c = k / XPITCH;
        int l = k - c * XPITCH;
        int src = l - PADW;
        float v = 0.0f;
        if (src >= 0 && src < LEN) v = x[(n * NCH + c) * LEN + src];
        Xp[k] = v;
    }
    __syncthreads();

    // ---- per-channel 9-tap dilated sums ----
    for (int k = tid; k < NCH * LEN; k += blockDim.x) {
        int c = k >> 10;
        int l = k & (LEN - 1);
        const float* xr = Xp + c * XPITCH + PADW + l;
        float s = 0.0f;
        #pragma unroll
        for (int t = 0; t < 9; t++) s += xr[(t - 4) * d];
        S[k] = s;
    }
    __syncthreads();

    const int warp = tid >> 5;
    const int lane = tid & 31;
    const int nf   = (i == 3) ? 29 : 30;
    const int boff = i * 2520;            // 84*30 per dilation (i=3 starts at 7560)

    // each warp owns 7 consecutive kernels
    for (int jj = 0; jj < 7; jj++) {
        const int j = warp * 7 + jj;

        const int cm = comb[j];
        const int oa = ((cm      ) & 255) - 4;
        const int ob = ((cm >>  8) & 255) - 4;
        const int oc = ((cm >> 16) & 255) - 4;

        const int* cir = ci + (i * NKER + j) * 3;
        const int c0 = cir[0], c1 = cir[1], c2 = cir[2];

        const float* X0 = Xp + c0 * XPITCH + PADW;
        const float* X1 = Xp + c1 * XPITCH + PADW;
        const float* X2 = Xp + c2 * XPITCH + PADW;
        const float* S0 = S + c0 * LEN;
        const float* S1 = S + c1 * LEN;
        const float* S2 = S + c2 * LEN;

        const bool even = (((i + j) & 1) == 0);
        const int start = even ? 0 : p;
        const int end   = even ? LEN : LEN - p;
        const float inv = 1.0f / (float)(end - start);

        // biases for this (dilation, kernel)
        const float* bp = biases + boff + j * nf;
        float bv[30];
        #pragma unroll
        for (int f = 0; f < 30; f++)
            bv[f] = (f < nf) ? bp[f] : CUDART_INF_F;   // inf => never counted

        int cnt[30];
        #pragma unroll
        for (int f = 0; f < 30; f++) cnt[f] = 0;

        const int da = oa * d, db = ob * d, dc = oc * d;

        for (int base = start; base < end; base += 32) {
            const int l = base + lane;
            float csum;
            if (l < end) {
                float A = X0[l + da] + X0[l + db] + X0[l + dc]
                        + X1[l + da] + X1[l + db] + X1[l + dc]
                        + X2[l + da] + X2[l + db] + X2[l + dc];
                float B = S0[l] + S1[l] + S2[l];
                csum = fmaf(3.0f, A, -B);
            } else {
                csum = -CUDART_INF_F;
            }
            #pragma unroll
            for (int f = 0; f < 30; f++)
                cnt[f] += (csum > bv[f]) ? 1 : 0;
        }

        // warp reduction: REDUX.SUM per counter
        #pragma unroll
        for (int f = 0; f < 30; f++)
            cnt[f] = __reduce_add_sync(0xffffffffu, cnt[f]);

        if (lane == 0) {
            float* op = out + n * TOTF + boff + j * nf;
            #pragma unroll
            for (int f = 0; f < 30; f++)
                if (f < nf) op[f] = (float)cnt[f] * inv;
        }
    }
}

extern "C" void kernel_launch(void* const* d_in, const int* in_sizes, int n_in,
                              void* d_out, int out_size)
{
    const float* x  = (const float*)d_in[0];
    const float* b  = (const float*)d_in[1];
    const int*   ci = (const int*)d_in[2];
    float* out = (float*)d_out;

    const int smem = (NCH * XPITCH + NCH * LEN) * 4 + NKER * 4;  // ~68 KB
    cudaFuncSetAttribute(minirocket_kernel,
                         cudaFuncAttributeMaxDynamicSharedMemorySize, smem);

    dim3 grid(4, NSAMP);
    minirocket_kernel<<<grid, 384, smem>>>(x, b, ci, out);
}

// round 2
// speedup vs baseline: 1.1699x; 1.1699x over previous
#include <cuda_runtime.h>
#include <math_constants.h>

// MiniRocket, round 2: quarter-L tiling for occupancy (4 blocks/SM, 16 warps)
// + load balance (1024 blocks), float2 vectorized inner loop for d>=2,
// partial counts -> device buffer -> tiny reduce kernel.

#define NCH    8
#define LEN    1024
#define NKER   84
#define QLEN   256
#define HALO   32
#define XPITCH (QLEN + 2*HALO)   // 320
#define JPAD   32                // padded feature stride for int4 stores
#define TOTF   9996

// [q][dil][n][j][JPAD] partial counts; every slot rewritten each launch.
__device__ int g_partial[4 * 4 * 64 * NKER * JPAD];   // ~11 MB

// ---------------------------------------------------------------------------
template<bool VEC, bool GUARD>
__device__ __forceinline__ void accumulate(
    const float* __restrict__ X0, const float* __restrict__ X1,
    const float* __restrict__ X2,
    const float* __restrict__ S0, const float* __restrict__ S1,
    const float* __restrict__ S2,
    int da, int db, int dc, int lane, int vlo, int vhi,
    const float* bv, int* cnt)
{
    #pragma unroll
    for (int it = 0; it < 4; it++) {
        float cx, cy;
        int u0, u1;
        if (VEC) {
            u0 = it * 64 + lane * 2;  u1 = u0 + 1;
            float2 a0 = *(const float2*)(X0 + u0 + da);
            float2 a1 = *(const float2*)(X0 + u0 + db);
            float2 a2 = *(const float2*)(X0 + u0 + dc);
            float2 a3 = *(const float2*)(X1 + u0 + da);
            float2 a4 = *(const float2*)(X1 + u0 + db);
            float2 a5 = *(const float2*)(X1 + u0 + dc);
            float2 a6 = *(const float2*)(X2 + u0 + da);
            float2 a7 = *(const float2*)(X2 + u0 + db);
            float2 a8 = *(const float2*)(X2 + u0 + dc);
            float2 s0 = *(const float2*)(S0 + u0);
            float2 s1 = *(const float2*)(S1 + u0);
            float2 s2 = *(const float2*)(S2 + u0);
            float Ax = ((a0.x+a1.x)+(a2.x+a3.x)) + ((a4.x+a5.x)+(a6.x+a7.x)) + a8.x;
            float Ay = ((a0.y+a1.y)+(a2.y+a3.y)) + ((a4.y+a5.y)+(a6.y+a7.y)) + a8.y;
            float Bx = s0.x + s1.x + s2.x;
            float By = s0.y + s1.y + s2.y;
            cx = fmaf(3.0f, Ax, -Bx);
            cy = fmaf(3.0f, Ay, -By);
        } else {
            u0 = it * 64 + lane;  u1 = u0 + 32;
            float Ax = ((X0[u0+da]+X0[u0+db])+(X0[u0+dc]+X1[u0+da]))
                     + ((X1[u0+db]+X1[u0+dc])+(X2[u0+da]+X2[u0+db])) + X2[u0+dc];
            float Ay = ((X0[u1+da]+X0[u1+db])+(X0[u1+dc]+X1[u1+da]))
                     + ((X1[u1+db]+X1[u1+dc])+(X2[u1+da]+X2[u1+db])) + X2[u1+dc];
            float Bx = S0[u0] + S1[u0] + S2[u0];
            float By = S0[u1] + S1[u1] + S2[u1];
            cx = fmaf(3.0f, Ax, -Bx);
            cy = fmaf(3.0f, Ay, -By);
        }
        if (GUARD) {
            if (u0 < vlo || u0 >= vhi) cx = -CUDART_INF_F;
            if (u1 < vlo || u1 >= vhi) cy = -CUDART_INF_F;
        }
        #pragma unroll
        for (int f = 0; f < 30; f++) {
            cnt[f] += (cx > bv[f]);
            cnt[f] += (cy > bv[f]);
        }
    }
}

// ---------------------------------------------------------------------------
// grid: (n_dils, 64 samples, 4 quarters), block: 128 threads (4 warps x 21 kernels)
template<bool VEC>
__global__ __launch_bounds__(128, 4)
void mr_main(const float* __restrict__ x,
             const float* __restrict__ biases,
             const int* __restrict__ ci,
             int dil_base)
{
    __shared__ float Xq[NCH][XPITCH];
    __shared__ float Sq[NCH][QLEN];
    __shared__ float bsh[NKER * 30];
    __shared__ int   comb[NKER];

    const int i  = blockIdx.x + dil_base;    // dilation index
    const int n  = blockIdx.y;               // sample
    const int q  = blockIdx.z;               // quarter
    const int d  = 1 << i;
    const int p  = 4 * d;
    const int qb = q * QLEN;
    const int tid = threadIdx.x;
    const int nf  = (i == 3) ? 29 : 30;
    const int boff = i * 2520;

    // 84 lexicographic 3-combinations of 0..8
    if (tid < NKER) {
        int t = 0, val = 0;
        for (int a = 0; a < 9; a++)
            for (int b2 = a + 1; b2 < 9; b2++)
                for (int c2 = b2 + 1; c2 < 9; c2++) {
                    if (t == tid) val = a | (b2 << 8) | (c2 << 16);
                    t++;
                }
        comb[tid] = val;
    }

    // stage the padded quarter of x
    for (int k = tid; k < NCH * XPITCH; k += 128) {
        int c = k / XPITCH;
        int u = k - c * XPITCH;
        int l = qb - HALO + u;
        Xq[c][u] = (l >= 0 && l < LEN) ? x[(n * NCH + c) * LEN + l] : 0.0f;
    }
    // stage this dilation's biases
    for (int k = tid; k < NKER * nf; k += 128) bsh[k] = biases[boff + k];
    __syncthreads();

    // per-channel 9-tap dilated sums over the quarter
    for (int k = tid; k < NCH * QLEN; k += 128) {
        int c = k >> 8;
        int u = k & (QLEN - 1);
        const float* xr = &Xq[c][u + HALO];
        float s = ((xr[-4*d] + xr[-3*d]) + (xr[-2*d] + xr[-d]))
                + ((xr[0]    + xr[d])    + (xr[2*d]  + xr[3*d])) + xr[4*d];
        Sq[c][u] = s;
    }
    __syncthreads();

    const int warp = tid >> 5;
    const int lane = tid & 31;

    for (int jj = 0; jj < 21; jj++) {
        const int j = warp * 21 + jj;

        const int cm = comb[j];
        const int da = (((cm      ) & 255) - 4) * d;
        const int db = (((cm >>  8) & 255) - 4) * d;
        const int dc = (((cm >> 16) & 255) - 4) * d;

        const int* cp = ci + (i * NKER + j) * 3;
        const int c0 = cp[0], c1 = cp[1], c2 = cp[2];

        const float* X0 = &Xq[c0][HALO];
        const float* X1 = &Xq[c1][HALO];
        const float* X2 = &Xq[c2][HALO];
        const float* S0 = &Sq[c0][0];
        const float* S1 = &Sq[c1][0];
        const float* S2 = &Sq[c2][0];

        float bv[30];
        int   cnt[30];
        #pragma unroll
        for (int f = 0; f < 30; f++) {
            bv[f]  = (f < nf) ? bsh[j * nf + f] : CUDART_INF_F;
            cnt[f] = 0;
        }

        const bool odd   = ((i + j) & 1) != 0;
        const bool guard = odd && (q == 0 || q == 3);
        const int vlo = (q == 0) ? p : 0;
        const int vhi = (q == 3) ? (QLEN - p) : QLEN;

        if (guard)
            accumulate<VEC, true >(X0, X1, X2, S0, S1, S2, da, db, dc,
                                   lane, vlo, vhi, bv, cnt);
        else
            accumulate<VEC, false>(X0, X1, X2, S0, S1, S2, da, db, dc,
                                   lane, vlo, vhi, bv, cnt);

        #pragma unroll
        for (int f = 0; f < 30; f++)
            cnt[f] = __reduce_add_sync(0xffffffffu, cnt[f]);

        if (lane == 0) {
            int* dst = g_partial + ((((q * 4 + i) * 64 + n) * NKER) + j) * JPAD;
            #pragma unroll
            for (int w = 0; w < 7; w++)
                *reinterpret_cast<int4*>(dst + w * 4) =
                    make_int4(cnt[w*4], cnt[w*4+1], cnt[w*4+2], cnt[w*4+3]);
            dst[28] = cnt[28];
            dst[29] = cnt[29];
        }
    }
}

// ---------------------------------------------------------------------------
// sum the 4 quarter partials, scale, scatter into the output layout
__global__ void mr_reduce(float* __restrict__ out)
{
    int t = blockIdx.x * 256 + threadIdx.x;
    const int TOT = 4 * 64 * NKER * 30;
    if (t >= TOT) return;

    int f = t % 30;  int r = t / 30;
    int j = r % NKER; r /= NKER;
    int n = r % 64;
    int i = r / 64;

    const int nf = (i == 3) ? 29 : 30;
    if (f >= nf) return;

    const int base   = (((i * 64 + n) * NKER) + j) * JPAD + f;
    const int stride = 4 * 64 * NKER * JPAD;
    int c = g_partial[base]
          + g_partial[base +     stride]
          + g_partial[base + 2 * stride]
          + g_partial[base + 3 * stride];

    const int dd = 1 << i;
    const bool even = ((i + j) & 1) == 0;
    const float inv = even ? (1.0f / 1024.0f)
                           : (1.0f / (1024.0f - 8.0f * (float)dd));

    out[n * TOTF + i * 2520 + j * nf + f] = (float)c * inv;
}

// ---------------------------------------------------------------------------
extern "C" void kernel_launch(void* const* d_in, const int* in_sizes, int n_in,
                              void* d_out, int out_size)
{
    const float* x  = (const float*)d_in[0];
    const float* b  = (const float*)d_in[1];
    const int*   ci = (const int*)d_in[2];
    float* out = (float*)d_out;

    // dilation 0 (d=1): odd tap offsets -> scalar loads; dilations 1-3: float2
    mr_main<false><<<dim3(1, 64, 4), 128>>>(x, b, ci, 0);
    mr_main<true ><<<dim3(3, 64, 4), 128>>>(x, b, ci, 1);

    const int TOT = 4 * 64 * NKER * 30;
    mr_reduce<<<(TOT + 255) / 256, 256>>>(out);
}

// round 3
// speedup vs baseline: 1.2198x; 1.0427x over previous
#include <cuda_runtime.h>
#include <math_constants.h>

// MiniRocket round 3: rank-bucketing PPV.
//   csum(l) exact as before; instead of 30 compare+adds per position, binary
//   search rank among sorted biases (5 steps) + per-lane byte histogram in
//   smem; per-kernel epilogue converts histogram -> exact counts.
// One full wave: 740 blocks = 148 SMs x 5 blocks, equal position-ranges.

#define NCH    8
#define LEN    1024
#define NKER   84
#define HALO   32
#define PITCHX 432
#define PITCHS 368
#define TOTF   9996

// partial counts [i][n][j][32]; finalize re-zeros after reading (graph-safe).
__device__ int g_partial[4 * 64 * NKER * 32];
__device__ float g_sbias[4 * NKER * 32];
__device__ unsigned char g_sperm[4 * NKER * 32];

// ---------------------------------------------------------------------------
// Sort the 30 biases of each (dilation, kernel) ascending; keep permutation.
// One warp per (i,j); all-pairs rank via shfl_xor. Pad to 32 with +inf.
__global__ void mr_sort(const float* __restrict__ biases)
{
    int b = blockIdx.x;                    // i*84 + j
    int i = b / NKER, j = b - i * NKER;
    int s = threadIdx.x;
    int nf = (i == 3) ? 29 : 30;
    float v = (s < nf) ? biases[i * 2520 + j * nf + s] : CUDART_INF_F;
    int rank = 0;
    #pragma unroll
    for (int k = 1; k < 32; k++) {
        float ov = __shfl_xor_sync(0xffffffffu, v, k);
        int o = s ^ k;
        rank += (ov < v || (ov == v && o < s)) ? 1 : 0;
    }
    g_sbias[b * 32 + rank] = v;
    g_sperm[b * 32 + rank] = (unsigned char)s;
}

// count of sorted entries < c   (5-step branchless lower bound over 32)
__device__ __forceinline__ int rank32(const float* __restrict__ sb, float c)
{
    int lo = (c > sb[15]) ? 16 : 0;
    lo += (c > sb[lo + 7]) ? 8 : 0;
    lo += (c > sb[lo + 3]) ? 4 : 0;
    lo += (c > sb[lo + 1]) ? 2 : 0;
    lo += (c > sb[lo])     ? 1 : 0;
    return lo;
}

// ---------------------------------------------------------------------------
__global__ __launch_bounds__(128, 5)
void mr_main(const float* __restrict__ x, const int* __restrict__ ci)
{
    __shared__ __align__(16) float Xq[NCH * PITCHX];
    __shared__ __align__(16) float Sq[NCH * PITCHS];
    __shared__ float sb[NKER * 32];
    __shared__ unsigned char sp[NKER * 32];
    __shared__ unsigned char hist[4 * 32 * 36];   // [warp][lane][36B] private rows
    __shared__ int comb[NKER];

    const int tid = threadIdx.x, warp = tid >> 5, lane = tid & 31;

    // block -> (dilation, local block, range). d=1 path is scalar (slower),
    // so it gets more, smaller blocks: 200/180/180/180 = 740 = 148*5.
    int bid = blockIdx.x;
    int i, bl, range;
    if (bid < 200) { i = 0; bl = bid; range = 328; }
    else { int r = bid - 200; i = 1 + r / 180; bl = r % 180; range = 365; }
    const int d = 1 << i, p = 4 * d;
    const int nf = (i == 3) ? 29 : 30;

    if (tid < NKER) {                      // 84 lexicographic triples of 0..8
        int t = 0, val = 0;
        for (int a = 0; a < 9; a++)
            for (int b2 = a + 1; b2 < 9; b2++)
                for (int c2 = b2 + 1; c2 < 9; c2++) {
                    if (t == tid) val = a | (b2 << 8) | (c2 << 16);
                    t++;
                }
        comb[tid] = val;
    }
    for (int k = tid; k < NKER * 32; k += 128) {
        sb[k] = g_sbias[i * NKER * 32 + k];
        sp[k] = g_sperm[i * NKER * 32 + k];
    }

    int g0 = bl * range;
    int g1 = min(g0 + range, 65536);
    int g = g0;
    while (g < g1) {                       // <= 2 sample-segments per block
        const int n = g >> 10;
        const int ls = g & 1023;
        const int seglen = min(LEN - ls, g1 - g);

        __syncthreads();
        for (int c = 0; c < NCH; c++) {    // stage padded segment of x[n]
            const float* xc = x + (n * NCH + c) * LEN;
            for (int u = tid; u < seglen + 2 * HALO; u += 128) {
                int l = ls - HALO + u;
                Xq[c * PITCHX + u] = (l >= 0 && l < LEN) ? xc[l] : 0.0f;
            }
        }
        __syncthreads();
        for (int c = 0; c < NCH; c++) {    // per-channel 9-tap dilated sums
            const float* xb = Xq + c * PITCHX + HALO;
            float* sc = Sq + c * PITCHS;
            for (int u = tid; u < seglen; u += 128) {
                float s = ((xb[u-4*d] + xb[u-3*d]) + (xb[u-2*d] + xb[u-d]))
                        + ((xb[u] + xb[u+d]) + (xb[u+2*d] + xb[u+3*d])) + xb[u+4*d];
                sc[u] = s;
            }
        }
        __syncthreads();

        unsigned char* hrow  = hist + (warp * 32 + lane) * 36;
        unsigned char* hwarp = hist + warp * 32 * 36;

        for (int jj = 0; jj < 21; jj++) {  // each warp owns 21 kernels
            const int j = warp * 21 + jj;
            const int cm = comb[j];
            const int da = (((cm      ) & 255) - 4) * d;
            const int db = (((cm >>  8) & 255) - 4) * d;
            const int dc = (((cm >> 16) & 255) - 4) * d;
            const int* cp = ci + (i * NKER + j) * 3;
            const int c0 = cp[0], c1 = cp[1], c2 = cp[2];
            const float* X0 = Xq + c0 * PITCHX + HALO;
            const float* X1 = Xq + c1 * PITCHX + HALO;
            const float* X2 = Xq + c2 * PITCHX + HALO;
            const float* S0 = Sq + c0 * PITCHS;
            const float* S1 = Sq + c1 * PITCHS;
            const float* S2 = Sq + c2 * PITCHS;
            const float* sbj = sb + j * 32;

            int vlo = 0, vhi = seglen;
            if ((i + j) & 1) {             // odd parity: interior [p, L-p)
                vlo = max(0, p - ls);
                vhi = min(seglen, LEN - p - ls);
            }

            __syncwarp();                  // prior epilogue reads done
            #pragma unroll
            for (int t = 0; t < 9; t++)
                *(unsigned*)(hrow + 4 * t) = 0u;

            if (i == 0) {                  // d=1: odd tap offsets -> scalar
                for (int u0 = lane; u0 < seglen; u0 += 64) {
                    const int u1 = u0 + 32;
                    float ax = ((X0[u0+da] + X0[u0+db]) + (X0[u0+dc] + X1[u0+da]))
                             + ((X1[u0+db] + X1[u0+dc]) + (X2[u0+da] + X2[u0+db]))
                             + X2[u0+dc];
                    float cx = fmaf(3.0f, ax, -(S0[u0] + S1[u0] + S2[u0]));
                    float ay = ((X0[u1+da] + X0[u1+db]) + (X0[u1+dc] + X1[u1+da]))
                             + ((X1[u1+db] + X1[u1+dc]) + (X2[u1+da] + X2[u1+db]))
                             + X2[u1+dc];
                    float cy = fmaf(3.0f, ay, -(S0[u1] + S1[u1] + S2[u1]));
                    if (u0 >= vlo && u0 < vhi) hrow[rank32(sbj, cx)]++;
                    if (u1 >= vlo && u1 < vhi) hrow[rank32(sbj, cy)]++;
                }
            } else {                       // even d: float2, aligned
                for (int u0 = 2 * lane; u0 < seglen; u0 += 64) {
                    float2 a0 = *(const float2*)(X0 + u0 + da);
                    float2 a1 = *(const float2*)(X0 + u0 + db);
                    float2 a2 = *(const float2*)(X0 + u0 + dc);
                    float2 a3 = *(const float2*)(X1 + u0 + da);
                    float2 a4 = *(const float2*)(X1 + u0 + db);
                    float2 a5 = *(const float2*)(X1 + u0 + dc);
                    float2 a6 = *(const float2*)(X2 + u0 + da);
                    float2 a7 = *(const float2*)(X2 + u0 + db);
                    float2 a8 = *(const float2*)(X2 + u0 + dc);
                    float2 s0 = *(const float2*)(S0 + u0);
                    float2 s1 = *(const float2*)(S1 + u0);
                    float2 s2 = *(const float2*)(S2 + u0);
                    float ax = ((a0.x+a1.x)+(a2.x+a3.x)) + ((a4.x+a5.x)+(a6.x+a7.x)) + a8.x;
                    float ay = ((a0.y+a1.y)+(a2.y+a3.y)) + ((a4.y+a5.y)+(a6.y+a7.y)) + a8.y;
                    float cx = fmaf(3.0f, ax, -(s0.x + s1.x + s2.x));
                    float cy = fmaf(3.0f, ay, -(s0.y + s1.y + s2.y));
                    if (u0 >= vlo && u0 < vhi) hrow[rank32(sbj, cx)]++;
                    const int u1 = u0 + 1;
                    if (u1 >= vlo && u1 < vhi) hrow[rank32(sbj, cy)]++;
                }
            }

            __syncwarp();                  // all rows written
            // bin `lane` summed over the 32 private rows (diagonal walk)
            int tot = 0;
            #pragma unroll
            for (int t = 0; t < 32; t++) {
                int l = (lane + t) & 31;
                tot += hwarp[l * 36 + lane];
            }
            // suffix scan: suf[k] = sum_{r>=k} tot[r]
            int suf = tot;
            #pragma unroll
            for (int s = 1; s < 32; s <<= 1) {
                int v = __shfl_down_sync(0xffffffffu, suf, s);
                if (lane < 32 - s) suf += v;
            }
            int cnts = __shfl_down_sync(0xffffffffu, suf, 1);  // lane s -> suf[s+1]
            if (lane < nf && cnts > 0) {
                int f = sp[j * 32 + lane]; // back to original feature order
                atomicAdd(&g_partial[((i * 64 + n) * NKER + j) * 32 + f], cnts);
            }
        }
        g += seglen;
    }
}

// ---------------------------------------------------------------------------
// scale counts into output; re-zero partials so every graph replay is identical
__global__ void mr_fin(float* __restrict__ out)
{
    int t = blockIdx.x * 256 + threadIdx.x;
    if (t >= 4 * 64 * NKER * 30) return;
    int f = t % 30;
    int r = t / 30;
    int j = r % NKER; r /= NKER;
    int n = r % 64;
    int i = r / 64;
    int idx = ((i * 64 + n) * NKER + j) * 32 + f;
    int c = g_partial[idx];
    g_partial[idx] = 0;
    int nf = (i == 3) ? 29 : 30;
    if (f >= nf) return;
    float inv = (((i + j) & 1) == 0)
              ? (1.0f / 1024.0f)
              : (1.0f / (1024.0f - 8.0f * (float)(1 << i)));
    out[n * TOTF + i * 2520 + j * nf + f] = (float)c * inv;
}

// ---------------------------------------------------------------------------
extern "C" void kernel_launch(void* const* d_in, const int* in_sizes, int n_in,
                              void* d_out, int out_size)
{
    const float* x  = (const float*)d_in[0];
    const float* b  = (const float*)d_in[1];
    const int*   ci = (const int*)d_in[2];
    float* out = (float*)d_out;

    mr_sort<<<4 * NKER, 32>>>(b);
    mr_main<<<740, 128>>>(x, ci);
    mr_fin<<<(4 * 64 * NKER * 30 + 255) / 256, 256>>>(out);
}